// round 14
// baseline (speedup 1.0000x reference)
#include <cuda_runtime.h>
#include <cuda_fp16.h>
#include <math.h>
#include <stdint.h>

#define BSZ   8
#define SEQ   512
#define DIM   768
#define NP    32
#define PE    200
#define EMB   128
#define VOCAB 30522
#define SPAN  20
#define NB    (BSZ*NP)        /* 256 span pairs */
#define NR    (NB*SPAN)       /* 5120 rows */
#define K1    1536            /* 2*DIM */
#define VROWS 30720           /* 120*256, padded vocab rows */

/* ---------------- scratch (no allocation allowed) ---------------- */
__device__ __align__(256) __half g_lr[NB*K1];
__device__ __align__(256) __half g_h1[NR*DIM];
__device__ __align__(256) __half g_h2[NR*DIM];
__device__ __align__(256) __half g_h3[NR*EMB];
__device__ __align__(256) __half g_W1T[DIM*K1];
__device__ __align__(256) __half g_W2T[DIM*DIM];
__device__ __align__(256) __half g_WpT[EMB*DIM];
__device__ __align__(256) __half g_Wd[VROWS*EMB];
__device__ float g_P[SPAN*DIM];
__device__ float g_pre2[NR*DIM];     /* split-K partial scratch / pre2 */

/* FRAG16: block = 16 rows x 16 k = 256 halves. Granule (16B) at (srow,t4)
 * holds m16n8k16 A-quad. For fixed r and k%4==0: (r,k),(r,k+1) adjacent
 * halves; (r,k+2),(r,k+3) at +8 halves. */
__device__ __forceinline__ size_t frag16_addr(int r, int k, int ld) {
    size_t blk = (size_t)((r >> 4) * (ld >> 4) + (k >> 4));
    int kk = k & 15;
    return (blk << 8) + (((r & 7) << 2) + ((kk >> 1) & 3)) * 8
         + ((((r >> 3) & 1) + ((kk >> 3) << 1)) << 1) + (kk & 1);
}

__device__ __forceinline__ float gelu_exact(float x) {
    return 0.5f * x * (1.0f + erff(x * 0.70710678118654752440f));
}
__device__ __forceinline__ __half h16(float x) { return __float2half_rn(x); }

__device__ __forceinline__ void mma_f16_16n8k16(float* c, const uint32_t* a,
                                                uint32_t b0, uint32_t b1) {
    asm volatile(
        "mma.sync.aligned.m16n8k16.row.col.f32.f16.f16.f32 "
        "{%0,%1,%2,%3}, {%4,%5,%6,%7}, {%8,%9}, {%0,%1,%2,%3};"
        : "+f"(c[0]), "+f"(c[1]), "+f"(c[2]), "+f"(c[3])
        : "r"(a[0]), "r"(a[1]), "r"(a[2]), "r"(a[3]), "r"(b0), "r"(b1));
}

__device__ __forceinline__ uint32_t smem_u32(const void* p) {
    uint32_t a;
    asm("{ .reg .u64 t; cvta.to.shared.u64 t, %1; cvt.u32.u64 %0, t; }" : "=r"(a) : "l"(p));
    return a;
}

/* =================== fp16 mma.sync GEMM (FRAG16, BK=64, 3-stage) =========
 * 256 threads / 8 warps. CTA tile 128 x BN.
 *  BN=128: warp tile 64x32 (acc 64 regs), 2 CTAs/SM.
 *  BN=256: warp tile 64x64 (acc 128 regs), 1 CTA/SM.
 * One __syncthreads per k-tile (3-stage: loads at iter kt overwrite stage
 * (kt-1)%3 whose readers passed the leading barrier of iter kt).
 */
template<int KC, int BN>
__global__ void __launch_bounds__(256, BN == 128 ? 2 : 1)
mgemm16(const __half* __restrict__ A, int lda,
        const __half* __restrict__ Bt, int ldb, int Nvalid,
        float* __restrict__ C, int ldc,
        const float* __restrict__ bias, int czstride) {
    constexpr int NK   = KC >> 6;        /* 64-K tiles */
    constexpr int ASTG = 8192;           /* halves per A stage */
    constexpr int BSTG = BN * 64;        /* halves per B stage */
    constexpr int BQ   = BN >> 6;        /* B quads per warp per kb (2|4) */
    constexpr int NT2  = BN >> 5;        /* n-fragments per warp (4|8)    */
    extern __shared__ __align__(16) __half sm16[];
    __half* As = sm16;                   /* [3][ASTG] */
    __half* Bs = sm16 + 3*ASTG;          /* [3][BSTG] */
    const uint32_t sbA = smem_u32(As);
    const uint32_t sbB = smem_u32(Bs);

    const int tid  = threadIdx.x;
    const int lane = tid & 31;
    const int wid  = tid >> 5;
    const int wr   = (wid & 1) * 64;
    const int wc   = (wid >> 1) * (BN >> 2);
    const int wrS  = (wid & 1) * 4;
    const int wcS  = (wid >> 1) * (BN >> 6);
    const int g8   = lane >> 2;
    const int t4   = lane & 3;

    const int mBase = blockIdx.y * 128;
    const int nBase = blockIdx.x * BN;
    const int mSlab = mBase >> 4;
    const int nSlab = nBase >> 4;
    const int k0    = blockIdx.z * KC;
    C += (size_t)blockIdx.z * czstride;
    const int ldaB = lda >> 4;
    const int ldbB = ldb >> 4;

    float acc[4][NT2][4];
    #pragma unroll
    for (int i = 0; i < 4; i++)
        #pragma unroll
        for (int j = 0; j < NT2; j++)
            #pragma unroll
            for (int q = 0; q < 4; q++) acc[i][j][q] = 0.f;

    auto loadA = [&](int s, int kt) {
        const int kbase = (k0 >> 4) + kt*4;
        #pragma unroll
        for (int i = 0; i < 4; i++) {
            int idx  = tid + i*256;
            int slab = idx >> 7;
            int kb   = (idx >> 5) & 3;
            int g    = idx & 31;
            const __half* src = A + (((size_t)(mSlab + slab)*ldaB + (kbase + kb)) << 8) + g*8;
            uint32_t d = sbA + (uint32_t)(s*ASTG + ((slab << 2) + kb)*256 + g*8)*2u;
            asm volatile("cp.async.cg.shared.global [%0], [%1], 16;" :: "r"(d), "l"(src));
        }
    };
    auto loadB = [&](int s, int kt) {
        const int kbase = (k0 >> 4) + kt*4;
        #pragma unroll
        for (int i = 0; i < (BN*8)/256; i++) {
            int idx  = tid + i*256;
            int slab = idx >> 7;
            int kb   = (idx >> 5) & 3;
            int g    = idx & 31;
            const __half* src = Bt + (((size_t)(nSlab + slab)*ldbB + (kbase + kb)) << 8) + g*8;
            uint32_t d = sbB + (uint32_t)(s*BSTG + ((slab << 2) + kb)*256 + g*8)*2u;
            asm volatile("cp.async.cg.shared.global [%0], [%1], 16;" :: "r"(d), "l"(src));
        }
    };

    loadA(0, 0); loadB(0, 0);
    asm volatile("cp.async.commit_group;");
    if (NK > 1) {
        loadA(1, 1); loadB(1, 1);
        asm volatile("cp.async.commit_group;");
    }

    const int lo = ((g8 << 2) + t4) * 8;

    auto compute_tile = [&](int sc) {
        const __half* as = As + sc*ASTG;
        const __half* bs = Bs + sc*BSTG;
        #pragma unroll
        for (int kb = 0; kb < 4; kb++) {
            uint4 aq[4], bq[BQ];
            #pragma unroll
            for (int mt = 0; mt < 4; mt++)
                aq[mt] = *(const uint4*)(as + (((wrS + mt) << 2) + kb)*256 + lo);
            #pragma unroll
            for (int p = 0; p < BQ; p++)
                bq[p] = *(const uint4*)(bs + (((wcS + p) << 2) + kb)*256 + lo);
            #pragma unroll
            for (int mt = 0; mt < 4; mt++) {
                #pragma unroll
                for (int p = 0; p < BQ; p++) {
                    mma_f16_16n8k16(acc[mt][2*p],   (const uint32_t*)&aq[mt], bq[p].x, bq[p].z);
                    mma_f16_16n8k16(acc[mt][2*p+1], (const uint32_t*)&aq[mt], bq[p].y, bq[p].w);
                }
            }
        }
    };

    if (NK <= 8) {
        #pragma unroll
        for (int kt = 0; kt < NK; kt++) {
            if (kt + 1 < NK)
                asm volatile("cp.async.wait_group 1;");
            else
                asm volatile("cp.async.wait_group 0;");
            __syncthreads();
            if (kt + 2 < NK) {
                loadA((kt + 2) % 3, kt + 2); loadB((kt + 2) % 3, kt + 2);
                asm volatile("cp.async.commit_group;");
            }
            compute_tile(kt % 3);
        }
    } else {
        int sc = 0;
        #pragma unroll 3
        for (int kt = 0; kt < NK; kt++) {
            if (kt + 1 < NK)
                asm volatile("cp.async.wait_group 1;");
            else
                asm volatile("cp.async.wait_group 0;");
            __syncthreads();
            if (kt + 2 < NK) {
                int sn = sc + 2; if (sn >= 3) sn -= 3;
                loadA(sn, kt + 2); loadB(sn, kt + 2);
                asm volatile("cp.async.commit_group;");
            }
            compute_tile(sc);
            if (++sc == 3) sc = 0;
        }
    }

    #pragma unroll
    for (int mt = 0; mt < 4; mt++) {
        int r0 = mBase + wr + mt*16 + g8;
        #pragma unroll
        for (int nt = 0; nt < NT2; nt++) {
            int cc = nBase + wc + nt*8 + t4*2;
            if (cc < Nvalid) {
                float bx = bias ? bias[cc]   : 0.f;
                float by = bias ? bias[cc+1] : 0.f;
                float2 v0 = make_float2(acc[mt][nt][0] + bx, acc[mt][nt][1] + by);
                float2 v1 = make_float2(acc[mt][nt][2] + bx, acc[mt][nt][3] + by);
                *(float2*)(C + (size_t)r0*ldc + cc)     = v0;
                *(float2*)(C + (size_t)(r0+8)*ldc + cc) = v1;
            }
        }
    }
}

/* =================== fused producer kernel ===================
 *  [0,1152)     transpose W1 -> g_W1T
 *  [1152,1728)  transpose W2 -> g_W2T
 *  [1728,1824)  transpose Wp -> g_WpT
 *  [1824,3744)  Wdec -> g_Wd (FRAG16 granules, zero pad to VROWS)
 *  [3744,4000)  gather lh/rh -> g_lr
 *  [4000,4060)  posproj -> g_P
 */
#define PREP_GRID 4060
__global__ void __launch_bounds__(256) k_prep(
    const float* __restrict__ hs, const int* __restrict__ pairs,
    const float* __restrict__ pos, const float* __restrict__ W1,
    const float* __restrict__ b1, const float* __restrict__ W2,
    const float* __restrict__ Wp, const float* __restrict__ Wdec) {
    __shared__ float smem_t[32*33];
    const int bx  = blockIdx.x;
    const int tid = threadIdx.x;

    if (bx < 1824) {
        const float* in; __half* out; int R, C, l, gx;
        if (bx < 1152)      { in = W1; out = g_W1T; R = K1;  C = DIM; l = bx;        gx = 24; }
        else if (bx < 1728) { in = W2; out = g_W2T; R = DIM; C = DIM; l = bx - 1152; gx = 24; }
        else                { in = Wp; out = g_WpT; R = DIM; C = EMB; l = bx - 1728; gx = 4;  }
        int c0 = (l % gx) * 32, r0 = (l / gx) * 32;
        int tx = tid & 31, ty = tid >> 5;
        float (*t)[33] = (float(*)[33])smem_t;
        #pragma unroll
        for (int dy = ty; dy < 32; dy += 8)
            t[dy][tx] = in[(size_t)(r0 + dy)*C + c0 + tx];
        __syncthreads();
        #pragma unroll
        for (int dy = ty; dy < 32; dy += 8)
            out[frag16_addr(c0 + dy, r0 + tx, R)] = h16(t[tx][dy]);
    } else if (bx < 3744) {
        int gid = (bx - 1824)*256 + tid;
        int blk = gid >> 5;
        int g   = gid & 31;
        int srow = g >> 2, t4 = g & 3;
        int R0 = (blk >> 3) << 4;
        int K0 = (blk & 7) << 4;
        int r0 = R0 + srow, r1 = r0 + 8;
        int kl = K0 + 2*t4, kh = kl + 8;
        float2 a0 = make_float2(0.f,0.f), a1 = a0, a2 = a0, a3 = a0;
        if (r0 < VOCAB) { a0 = *(const float2*)(Wdec + (size_t)r0*EMB + kl);
                          a2 = *(const float2*)(Wdec + (size_t)r0*EMB + kh); }
        if (r1 < VOCAB) { a1 = *(const float2*)(Wdec + (size_t)r1*EMB + kl);
                          a3 = *(const float2*)(Wdec + (size_t)r1*EMB + kh); }
        __half2 h0 = __floats2half2_rn(a0.x, a0.y);
        __half2 h1 = __floats2half2_rn(a1.x, a1.y);
        __half2 h2 = __floats2half2_rn(a2.x, a2.y);
        __half2 h3 = __floats2half2_rn(a3.x, a3.y);
        uint4 u = make_uint4(*(uint32_t*)&h0, *(uint32_t*)&h1, *(uint32_t*)&h2, *(uint32_t*)&h3);
        *(uint4*)(g_Wd + ((size_t)blk << 8) + (size_t)g*8) = u;
    } else if (bx < 4000) {
        if (tid < 192) {
            int p = bx - 3744;
            int l0 = pairs[p*2 + 0];
            int r0 = pairs[p*2 + 1];
            int b  = p / NP;
            const float* hl = hs + ((size_t)b*SEQ + l0)*DIM;
            const float* hr = hs + ((size_t)b*SEQ + r0)*DIM;
            int k = tid * 4;
            float4 vl = *(const float4*)(hl + k);
            float4 vr = *(const float4*)(hr + k);
            __half2 l01 = __floats2half2_rn(vl.x, vl.y);
            __half2 l23 = __floats2half2_rn(vl.z, vl.w);
            __half2 r01 = __floats2half2_rn(vr.x, vr.y);
            __half2 r23 = __floats2half2_rn(vr.z, vr.w);
            size_t aL = frag16_addr(p, k, K1);
            size_t aR = frag16_addr(p, DIM + k, K1);
            *(__half2*)(g_lr + aL)     = l01;
            *(__half2*)(g_lr + aL + 8) = l23;
            *(__half2*)(g_lr + aR)     = r01;
            *(__half2*)(g_lr + aR + 8) = r23;
        }
    } else {
        int loc = bx - 4000;
        int l = loc / 3, sub = loc % 3;
        float* sp = smem_t;
        for (int t2 = tid; t2 < PE; t2 += 256) sp[t2] = pos[l*PE + t2];
        __syncthreads();
        int j = sub*256 + tid;
        float acc = b1[j];
        const float* w = W1 + (size_t)K1*DIM + j;
        #pragma unroll 8
        for (int t2 = 0; t2 < PE; t2++) acc += sp[t2] * w[(size_t)t2*DIM];
        g_P[l*DIM + j] = acc;
    }
}

/* =================== LN kernels: 192 thr x 4 consecutive j =============== */
__device__ __forceinline__ void block_reduce2_192(float& s, float& sq) {
    __shared__ float ss[6], ssq[6];
    #pragma unroll
    for (int o = 16; o > 0; o >>= 1) {
        s  += __shfl_xor_sync(0xffffffffu, s,  o);
        sq += __shfl_xor_sync(0xffffffffu, sq, o);
    }
    int w = threadIdx.x >> 5;
    if ((threadIdx.x & 31) == 0) { ss[w] = s; ssq[w] = sq; }
    __syncthreads();
    s = 0.f; sq = 0.f;
    #pragma unroll
    for (int i = 0; i < 6; i++) { s += ss[i]; sq += ssq[i]; }
}

__global__ void __launch_bounds__(192) k_fuse1(const float* __restrict__ part,
                        const float* __restrict__ g1, const float* __restrict__ be1) {
    int r = blockIdx.x;
    int p = r / SPAN, l = r % SPAN;
    int j = threadIdx.x * 4;
    float4 a4 = *(const float4*)(g_P + (size_t)l*DIM + j);
    float a[4] = {a4.x, a4.y, a4.z, a4.w};
    #pragma unroll
    for (int z = 0; z < 8; z++) {
        float4 pz = *(const float4*)(part + (size_t)z*(NB*DIM) + (size_t)p*DIM + j);
        a[0] += pz.x; a[1] += pz.y; a[2] += pz.z; a[3] += pz.w;
    }
    float v[4];
    float s = 0.f, sq = 0.f;
    #pragma unroll
    for (int q = 0; q < 4; q++) {
        v[q] = gelu_exact(a[q]); s += v[q]; sq += v[q]*v[q];
    }
    block_reduce2_192(s, sq);
    float mean = s * (1.0f/DIM);
    float var  = sq * (1.0f/DIM) - mean*mean;
    float rstd = rsqrtf(var + 1e-12f);
    float4 gg = *(const float4*)(g1 + j);
    float4 bb = *(const float4*)(be1 + j);
    float o0 = (v[0]-mean)*rstd*gg.x + bb.x;
    float o1 = (v[1]-mean)*rstd*gg.y + bb.y;
    float o2 = (v[2]-mean)*rstd*gg.z + bb.z;
    float o3 = (v[3]-mean)*rstd*gg.w + bb.w;
    size_t ad = frag16_addr(r, j, DIM);
    *(__half2*)(g_h1 + ad)     = __floats2half2_rn(o0, o1);
    *(__half2*)(g_h1 + ad + 8) = __floats2half2_rn(o2, o3);
}

__global__ void __launch_bounds__(192) k_gelu_ln(const float* __restrict__ in,
                          const float* __restrict__ g, const float* __restrict__ be) {
    int r = blockIdx.x;
    int j = threadIdx.x * 4;
    float4 a4 = *(const float4*)(in + (size_t)r*DIM + j);
    float v[4];
    float s = 0.f, sq = 0.f;
    v[0] = gelu_exact(a4.x); v[1] = gelu_exact(a4.y);
    v[2] = gelu_exact(a4.z); v[3] = gelu_exact(a4.w);
    #pragma unroll
    for (int q = 0; q < 4; q++) { s += v[q]; sq += v[q]*v[q]; }
    block_reduce2_192(s, sq);
    float mean = s * (1.0f/DIM);
    float var  = sq * (1.0f/DIM) - mean*mean;
    float rstd = rsqrtf(var + 1e-12f);
    float4 gg = *(const float4*)(g + j);
    float4 bb = *(const float4*)(be + j);
    float o0 = (v[0]-mean)*rstd*gg.x + bb.x;
    float o1 = (v[1]-mean)*rstd*gg.y + bb.y;
    float o2 = (v[2]-mean)*rstd*gg.z + bb.z;
    float o3 = (v[3]-mean)*rstd*gg.w + bb.w;
    size_t ad = frag16_addr(r, j, DIM);
    *(__half2*)(g_h2 + ad)     = __floats2half2_rn(o0, o1);
    *(__half2*)(g_h2 + ad + 8) = __floats2half2_rn(o2, o3);
}

__global__ void __launch_bounds__(256) k_reduceh3(const float* __restrict__ part,
                                                  const float* __restrict__ bp) {
    int i = (blockIdx.x*256 + threadIdx.x) * 4;
    float4 b4 = *(const float4*)(bp + (i & 127));
    float s0 = b4.x, s1 = b4.y, s2 = b4.z, s3 = b4.w;
    #pragma unroll
    for (int z = 0; z < 4; z++) {
        float4 pz = *(const float4*)(part + (size_t)z*(NR*EMB) + i);
        s0 += pz.x; s1 += pz.y; s2 += pz.z; s3 += pz.w;
    }
    size_t ad = frag16_addr(i >> 7, i & 127, EMB);
    *(__half2*)(g_h3 + ad)     = __floats2half2_rn(s0, s1);
    *(__half2*)(g_h3 + ad + 8) = __floats2half2_rn(s2, s3);
}

/* ---------------- host launch ---------------- */
extern "C" void kernel_launch(void* const* d_in, const int* in_sizes, int n_in,
                              void* d_out, int out_size) {
    const float* hs    = (const float*)d_in[0];
    const int*   pairs = (const int*)  d_in[1];
    const float* pos   = (const float*)d_in[2];
    const float* W1    = (const float*)d_in[3];
    const float* b1    = (const float*)d_in[4];
    const float* g1    = (const float*)d_in[5];
    const float* be1   = (const float*)d_in[6];
    const float* W2    = (const float*)d_in[7];
    const float* b2    = (const float*)d_in[8];
    const float* g2    = (const float*)d_in[9];
    const float* be2   = (const float*)d_in[10];
    const float* Wp    = (const float*)d_in[11];
    const float* bp    = (const float*)d_in[12];
    const float* Wdec  = (const float*)d_in[13];
    float* out = (float*)d_out;
    (void)in_sizes; (void)n_in; (void)out_size;

    __half *p_lr, *p_h1, *p_h2, *p_h3, *p_W1T, *p_W2T, *p_WpT, *p_Wd;
    float *p_pre2;
    cudaGetSymbolAddress((void**)&p_lr,   g_lr);
    cudaGetSymbolAddress((void**)&p_h1,   g_h1);
    cudaGetSymbolAddress((void**)&p_h2,   g_h2);
    cudaGetSymbolAddress((void**)&p_h3,   g_h3);
    cudaGetSymbolAddress((void**)&p_W1T,  g_W1T);
    cudaGetSymbolAddress((void**)&p_W2T,  g_W2T);
    cudaGetSymbolAddress((void**)&p_WpT,  g_WpT);
    cudaGetSymbolAddress((void**)&p_Wd,   g_Wd);
    cudaGetSymbolAddress((void**)&p_pre2, g_pre2);

    const int SM128 = 3 * (8192 + 8192)  * 2;   /*  98304 B */
    const int SM256 = 3 * (8192 + 16384) * 2;   /* 147456 B */
    cudaFuncSetAttribute((const void*)mgemm16<192,128>, cudaFuncAttributeMaxDynamicSharedMemorySize, SM128);
    cudaFuncSetAttribute((const void*)mgemm16<768,128>, cudaFuncAttributeMaxDynamicSharedMemorySize, SM128);
    cudaFuncSetAttribute((const void*)mgemm16<128,256>, cudaFuncAttributeMaxDynamicSharedMemorySize, SM256);

    /* 0) one fused producer launch */
    k_prep<<<PREP_GRID, 256>>>(hs, pairs, pos, W1, b1, W2, Wp, Wdec);

    /* 1) A-partials = g_lr @ W1[0:1536]  split-K x8 (into g_pre2) */
    mgemm16<192,128><<<dim3(DIM/128, NB/128, 8), 256, SM128>>>(
        p_lr, K1, p_W1T, K1, DIM, p_pre2, DIM, nullptr, NB*DIM);

    /* 2) h1 = LN(gelu(sum partials + P)) -> FRAG16 */
    k_fuse1<<<NR, 192>>>(p_pre2, g1, be1);

    /* 3) pre2 = h1 @ W2 + b2 ; h2 = LN(gelu(pre2)) -> FRAG16 */
    mgemm16<768,128><<<dim3(DIM/128, NR/128, 1), 256, SM128>>>(
        p_h1, DIM, p_W2T, DIM, DIM, p_pre2, DIM, b2, 0);
    k_gelu_ln<<<NR, 192>>>(p_pre2, g2, be2);

    /* 4) h3 = h2 @ Wp + bp  split-K x4 -> FRAG16 via reduce */
    mgemm16<192,128><<<dim3(EMB/128, NR/128, 4), 256, SM128>>>(
        p_h2, DIM, p_WpT, DIM, EMB, p_pre2, EMB, nullptr, NR*EMB);
    k_reduceh3<<<(NR*EMB)/1024, 256>>>(p_pre2, bp);

    /* 5) out = h3 @ Wd^T (M=5120 N=30522(+pad to 30720) K=128), BN=256 */
    mgemm16<128,256><<<dim3(VROWS/256, NR/128, 1), 256, SM256>>>(
        p_h3, EMB, p_Wd, EMB, VOCAB, out, VOCAB, nullptr, 0);
}

// round 15
// speedup vs baseline: 1.2121x; 1.2121x over previous
#include <cuda_runtime.h>
#include <cuda_fp16.h>
#include <math.h>
#include <stdint.h>

#define BSZ   8
#define SEQ   512
#define DIM   768
#define NP    32
#define PE    200
#define EMB   128
#define VOCAB 30522
#define SPAN  20
#define NB    (BSZ*NP)        /* 256 span pairs */
#define NR    (NB*SPAN)       /* 5120 rows */
#define K1    1536            /* 2*DIM */
#define VROWS 30592           /* 239*128, padded vocab rows */
#define STRIP 2               /* M-tiles per CTA in mgemm4 */

/* ---------------- scratch (no allocation allowed) ---------------- */
__device__ __align__(256) __half g_lr[NB*K1];
__device__ __align__(256) __half g_h1[NR*DIM];
__device__ __align__(256) __half g_h2[NR*DIM];
__device__ __align__(256) __half g_h3[NR*EMB];
__device__ __align__(256) __half g_W1T[DIM*K1];
__device__ __align__(256) __half g_W2T[DIM*DIM];
__device__ __align__(256) __half g_WpT[EMB*DIM];
__device__ __align__(256) __half g_Wd[VROWS*EMB];
__device__ float g_P[SPAN*DIM];
__device__ float g_pre2[NR*DIM];     /* split-K partial scratch / pre2 */

/* FRAG16: block = 16 rows x 16 k = 256 halves. Granule (16B) at (srow,t4)
 * holds m16n8k16 A-quad. */
__device__ __forceinline__ size_t frag16_addr(int r, int k, int ld) {
    size_t blk = (size_t)((r >> 4) * (ld >> 4) + (k >> 4));
    int kk = k & 15;
    return (blk << 8) + (((r & 7) << 2) + ((kk >> 1) & 3)) * 8
         + ((((r >> 3) & 1) + ((kk >> 3) << 1)) << 1) + (kk & 1);
}

__device__ __forceinline__ float gelu_exact(float x) {
    return 0.5f * x * (1.0f + erff(x * 0.70710678118654752440f));
}
__device__ __forceinline__ __half h16(float x) { return __float2half_rn(x); }

__device__ __forceinline__ void mma_f16_16n8k16(float* c, const uint32_t* a,
                                                uint32_t b0, uint32_t b1) {
    asm volatile(
        "mma.sync.aligned.m16n8k16.row.col.f32.f16.f16.f32 "
        "{%0,%1,%2,%3}, {%4,%5,%6,%7}, {%8,%9}, {%0,%1,%2,%3};"
        : "+f"(c[0]), "+f"(c[1]), "+f"(c[2]), "+f"(c[3])
        : "r"(a[0]), "r"(a[1]), "r"(a[2]), "r"(a[3]), "r"(b0), "r"(b1));
}

__device__ __forceinline__ uint32_t smem_u32(const void* p) {
    uint32_t a;
    asm("{ .reg .u64 t; cvta.to.shared.u64 t, %1; cvt.u32.u64 %0, t; }" : "=r"(a) : "l"(p));
    return a;
}

/* =================== fp16 mma.sync GEMM (FRAG16, BK=64, 3-stage) =========
 * 256 threads / 8 warps, warp tile 64x32. CTA tile 128x128, BK=64.
 * Stage = 16KB A + 16KB B; 3 stages = 96KB; 2 CTAs/SM. One barrier/k-tile.
 */
template<int KC>
__global__ void __launch_bounds__(256, 2)
mgemm16(const __half* __restrict__ A, int lda,
        const __half* __restrict__ Bt, int ldb, int Nvalid,
        float* __restrict__ C, int ldc,
        const float* __restrict__ bias, int czstride) {
    constexpr int NK = KC >> 6;
    constexpr int STG = 8192;
    extern __shared__ __align__(16) __half sm16[];
    __half* As = sm16;
    __half* Bs = sm16 + 3*STG;
    const uint32_t sbA = smem_u32(As);
    const uint32_t sbB = smem_u32(Bs);

    const int tid  = threadIdx.x;
    const int lane = tid & 31;
    const int wid  = tid >> 5;
    const int wr   = (wid & 1) * 64;
    const int wc   = (wid >> 1) * 32;
    const int wrS  = (wid & 1) * 4;
    const int wcS  = (wid >> 1) * 2;
    const int g8   = lane >> 2;
    const int t4   = lane & 3;

    const int mBase = blockIdx.y * 128;
    const int nBase = blockIdx.x * 128;
    const int mSlab = mBase >> 4;
    const int nSlab = nBase >> 4;
    const int k0    = blockIdx.z * KC;
    C += (size_t)blockIdx.z * czstride;
    const int ldaB = lda >> 4;
    const int ldbB = ldb >> 4;

    float acc[4][4][4];
    #pragma unroll
    for (int i = 0; i < 4; i++)
        #pragma unroll
        for (int j = 0; j < 4; j++)
            #pragma unroll
            for (int q = 0; q < 4; q++) acc[i][j][q] = 0.f;

    auto loadA = [&](int s, int kt) {
        const int kbase = (k0 >> 4) + kt*4;
        #pragma unroll
        for (int i = 0; i < 4; i++) {
            int idx  = tid + i*256;
            int slab = idx >> 7;
            int kb   = (idx >> 5) & 3;
            int g    = idx & 31;
            const __half* src = A + (((size_t)(mSlab + slab)*ldaB + (kbase + kb)) << 8) + g*8;
            uint32_t d = sbA + (uint32_t)(s*STG + ((slab << 2) + kb)*256 + g*8)*2u;
            asm volatile("cp.async.cg.shared.global [%0], [%1], 16;" :: "r"(d), "l"(src));
        }
    };
    auto loadB = [&](int s, int kt) {
        const int kbase = (k0 >> 4) + kt*4;
        #pragma unroll
        for (int i = 0; i < 4; i++) {
            int idx  = tid + i*256;
            int slab = idx >> 7;
            int kb   = (idx >> 5) & 3;
            int g    = idx & 31;
            const __half* src = Bt + (((size_t)(nSlab + slab)*ldbB + (kbase + kb)) << 8) + g*8;
            uint32_t d = sbB + (uint32_t)(s*STG + ((slab << 2) + kb)*256 + g*8)*2u;
            asm volatile("cp.async.cg.shared.global [%0], [%1], 16;" :: "r"(d), "l"(src));
        }
    };

    loadA(0, 0); loadB(0, 0);
    asm volatile("cp.async.commit_group;");
    if (NK > 1) {
        loadA(1, 1); loadB(1, 1);
        asm volatile("cp.async.commit_group;");
    }

    const int lo = ((g8 << 2) + t4) * 8;

    auto compute_tile = [&](int sc) {
        const __half* as = As + sc*STG;
        const __half* bs = Bs + sc*STG;
        #pragma unroll
        for (int kb = 0; kb < 4; kb++) {
            uint4 aq[4], bq[2];
            #pragma unroll
            for (int mt = 0; mt < 4; mt++)
                aq[mt] = *(const uint4*)(as + (((wrS + mt) << 2) + kb)*256 + lo);
            #pragma unroll
            for (int p = 0; p < 2; p++)
                bq[p] = *(const uint4*)(bs + (((wcS + p) << 2) + kb)*256 + lo);
            #pragma unroll
            for (int mt = 0; mt < 4; mt++) {
                #pragma unroll
                for (int p = 0; p < 2; p++) {
                    mma_f16_16n8k16(acc[mt][2*p],   (const uint32_t*)&aq[mt], bq[p].x, bq[p].z);
                    mma_f16_16n8k16(acc[mt][2*p+1], (const uint32_t*)&aq[mt], bq[p].y, bq[p].w);
                }
            }
        }
    };

    if (NK <= 8) {
        #pragma unroll
        for (int kt = 0; kt < NK; kt++) {
            if (kt + 1 < NK)
                asm volatile("cp.async.wait_group 1;");
            else
                asm volatile("cp.async.wait_group 0;");
            __syncthreads();
            if (kt + 2 < NK) {
                loadA((kt + 2) % 3, kt + 2); loadB((kt + 2) % 3, kt + 2);
                asm volatile("cp.async.commit_group;");
            }
            compute_tile(kt % 3);
        }
    } else {
        int sc = 0;
        #pragma unroll 3
        for (int kt = 0; kt < NK; kt++) {
            if (kt + 1 < NK)
                asm volatile("cp.async.wait_group 1;");
            else
                asm volatile("cp.async.wait_group 0;");
            __syncthreads();
            if (kt + 2 < NK) {
                int sn = sc + 2; if (sn >= 3) sn -= 3;
                loadA(sn, kt + 2); loadB(sn, kt + 2);
                asm volatile("cp.async.commit_group;");
            }
            compute_tile(sc);
            if (++sc == 3) sc = 0;
        }
    }

    #pragma unroll
    for (int mt = 0; mt < 4; mt++) {
        int r0 = mBase + wr + mt*16 + g8;
        #pragma unroll
        for (int nt = 0; nt < 4; nt++) {
            int cc = nBase + wc + nt*8 + t4*2;
            if (cc < Nvalid) {
                float bx = bias ? bias[cc]   : 0.f;
                float by = bias ? bias[cc+1] : 0.f;
                float2 v0 = make_float2(acc[mt][nt][0] + bx, acc[mt][nt][1] + by);
                float2 v1 = make_float2(acc[mt][nt][2] + bx, acc[mt][nt][3] + by);
                *(float2*)(C + (size_t)r0*ldc + cc)     = v0;
                *(float2*)(C + (size_t)(r0+8)*ldc + cc) = v1;
            }
        }
    }
}

/* =================== GEMM4: persistent-B strip kernel =====================
 * out[M, VOCAB] = h3[M,128] @ Wd[V,128]^T. K=128 (2 x 64-K buffers).
 * Each CTA: one N-tile (B kept in SMEM for the whole CTA), STRIP M-tiles.
 * Next M-tile's A-loads issued BEFORE the epilogue (overlap with stores).
 * SMEM: B 2x16KB + A 2x16KB = 64KB -> 2 CTAs/SM.
 */
__global__ void __launch_bounds__(256, 2)
mgemm4(const __half* __restrict__ A, const __half* __restrict__ Bt,
       int Nvalid, float* __restrict__ C, int ldc) {
    constexpr int STG = 8192;
    extern __shared__ __align__(16) __half sm16[];
    __half* Bs = sm16;            /* [2][8192] persistent */
    __half* As = sm16 + 2*STG;    /* [2][8192] per M-tile */
    const uint32_t sbA = smem_u32(As);
    const uint32_t sbB = smem_u32(Bs);

    const int tid  = threadIdx.x;
    const int lane = tid & 31;
    const int wid  = tid >> 5;
    const int wr   = (wid & 1) * 64;
    const int wc   = (wid >> 1) * 32;
    const int wrS  = (wid & 1) * 4;
    const int wcS  = (wid >> 1) * 2;
    const int g8   = lane >> 2;
    const int t4   = lane & 3;

    const int nBase = blockIdx.x * 128;
    const int nSlab = nBase >> 4;
    const int mTile0 = blockIdx.y * STRIP;

    auto loadB = [&](int kt) {
        const int kbase = kt*4;
        #pragma unroll
        for (int i = 0; i < 4; i++) {
            int idx  = tid + i*256;
            int slab = idx >> 7;
            int kb   = (idx >> 5) & 3;
            int g    = idx & 31;
            const __half* src = Bt + (((size_t)(nSlab + slab)*8 + (kbase + kb)) << 8) + g*8;
            uint32_t d = sbB + (uint32_t)(kt*STG + ((slab << 2) + kb)*256 + g*8)*2u;
            asm volatile("cp.async.cg.shared.global [%0], [%1], 16;" :: "r"(d), "l"(src));
        }
    };
    auto loadA = [&](int mTile, int kt) {
        const int mSlab = mTile << 3;
        const int kbase = kt*4;
        #pragma unroll
        for (int i = 0; i < 4; i++) {
            int idx  = tid + i*256;
            int slab = idx >> 7;
            int kb   = (idx >> 5) & 3;
            int g    = idx & 31;
            const __half* src = A + (((size_t)(mSlab + slab)*8 + (kbase + kb)) << 8) + g*8;
            uint32_t d = sbA + (uint32_t)(kt*STG + ((slab << 2) + kb)*256 + g*8)*2u;
            asm volatile("cp.async.cg.shared.global [%0], [%1], 16;" :: "r"(d), "l"(src));
        }
    };

    /* prologue: full B + first M-tile's A */
    loadB(0); loadB(1);
    loadA(mTile0, 0); loadA(mTile0, 1);
    asm volatile("cp.async.commit_group;");
    asm volatile("cp.async.wait_group 0;");
    __syncthreads();

    const int lo = ((g8 << 2) + t4) * 8;

    for (int ms = 0; ms < STRIP; ms++) {
        float acc[4][4][4];
        #pragma unroll
        for (int i = 0; i < 4; i++)
            #pragma unroll
            for (int j = 0; j < 4; j++)
                #pragma unroll
                for (int q = 0; q < 4; q++) acc[i][j][q] = 0.f;

        #pragma unroll
        for (int kt = 0; kt < 2; kt++) {
            const __half* as = As + kt*STG;
            const __half* bs = Bs + kt*STG;
            #pragma unroll
            for (int kb = 0; kb < 4; kb++) {
                uint4 aq[4], bq[2];
                #pragma unroll
                for (int mt = 0; mt < 4; mt++)
                    aq[mt] = *(const uint4*)(as + (((wrS + mt) << 2) + kb)*256 + lo);
                #pragma unroll
                for (int p = 0; p < 2; p++)
                    bq[p] = *(const uint4*)(bs + (((wcS + p) << 2) + kb)*256 + lo);
                #pragma unroll
                for (int mt = 0; mt < 4; mt++) {
                    #pragma unroll
                    for (int p = 0; p < 2; p++) {
                        mma_f16_16n8k16(acc[mt][2*p],   (const uint32_t*)&aq[mt], bq[p].x, bq[p].z);
                        mma_f16_16n8k16(acc[mt][2*p+1], (const uint32_t*)&aq[mt], bq[p].y, bq[p].w);
                    }
                }
            }
        }

        /* prefetch next M-tile's A before epilogue (overlap with stores) */
        if (ms + 1 < STRIP) {
            __syncthreads();   /* all warps done reading As */
            loadA(mTile0 + ms + 1, 0); loadA(mTile0 + ms + 1, 1);
            asm volatile("cp.async.commit_group;");
        }

        int mBase = (mTile0 + ms) * 128;
        #pragma unroll
        for (int mt = 0; mt < 4; mt++) {
            int r0 = mBase + wr + mt*16 + g8;
            #pragma unroll
            for (int nt = 0; nt < 4; nt++) {
                int cc = nBase + wc + nt*8 + t4*2;
                if (cc < Nvalid) {
                    float2 v0 = make_float2(acc[mt][nt][0], acc[mt][nt][1]);
                    float2 v1 = make_float2(acc[mt][nt][2], acc[mt][nt][3]);
                    *(float2*)(C + (size_t)r0*ldc + cc)     = v0;
                    *(float2*)(C + (size_t)(r0+8)*ldc + cc) = v1;
                }
            }
        }

        if (ms + 1 < STRIP) {
            asm volatile("cp.async.wait_group 0;");
            __syncthreads();
        }
    }
}

/* =================== fused producer kernel =================== */
#define PREP_GRID 4052
__global__ void __launch_bounds__(256) k_prep(
    const float* __restrict__ hs, const int* __restrict__ pairs,
    const float* __restrict__ pos, const float* __restrict__ W1,
    const float* __restrict__ b1, const float* __restrict__ W2,
    const float* __restrict__ Wp, const float* __restrict__ Wdec) {
    __shared__ float smem_t[32*33];
    const int bx  = blockIdx.x;
    const int tid = threadIdx.x;

    if (bx < 1824) {
        const float* in; __half* out; int R, C, l, gx;
        if (bx < 1152)      { in = W1; out = g_W1T; R = K1;  C = DIM; l = bx;        gx = 24; }
        else if (bx < 1728) { in = W2; out = g_W2T; R = DIM; C = DIM; l = bx - 1152; gx = 24; }
        else                { in = Wp; out = g_WpT; R = DIM; C = EMB; l = bx - 1728; gx = 4;  }
        int c0 = (l % gx) * 32, r0 = (l / gx) * 32;
        int tx = tid & 31, ty = tid >> 5;
        float (*t)[33] = (float(*)[33])smem_t;
        #pragma unroll
        for (int dy = ty; dy < 32; dy += 8)
            t[dy][tx] = in[(size_t)(r0 + dy)*C + c0 + tx];
        __syncthreads();
        #pragma unroll
        for (int dy = ty; dy < 32; dy += 8)
            out[frag16_addr(c0 + dy, r0 + tx, R)] = h16(t[tx][dy]);
    } else if (bx < 3736) {
        int gid = (bx - 1824)*256 + tid;
        int blk = gid >> 5;
        int g   = gid & 31;
        int srow = g >> 2, t4 = g & 3;
        int R0 = (blk >> 3) << 4;
        int K0 = (blk & 7) << 4;
        int r0 = R0 + srow, r1 = r0 + 8;
        int kl = K0 + 2*t4, kh = kl + 8;
        float2 a0 = make_float2(0.f,0.f), a1 = a0, a2 = a0, a3 = a0;
        if (r0 < VOCAB) { a0 = *(const float2*)(Wdec + (size_t)r0*EMB + kl);
                          a2 = *(const float2*)(Wdec + (size_t)r0*EMB + kh); }
        if (r1 < VOCAB) { a1 = *(const float2*)(Wdec + (size_t)r1*EMB + kl);
                          a3 = *(const float2*)(Wdec + (size_t)r1*EMB + kh); }
        __half2 h0 = __floats2half2_rn(a0.x, a0.y);
        __half2 h1 = __floats2half2_rn(a1.x, a1.y);
        __half2 h2 = __floats2half2_rn(a2.x, a2.y);
        __half2 h3 = __floats2half2_rn(a3.x, a3.y);
        uint4 u = make_uint4(*(uint32_t*)&h0, *(uint32_t*)&h1, *(uint32_t*)&h2, *(uint32_t*)&h3);
        *(uint4*)(g_Wd + ((size_t)blk << 8) + (size_t)g*8) = u;
    } else if (bx < 3992) {
        if (tid < 192) {
            int p = bx - 3736;
            int l0 = pairs[p*2 + 0];
            int r0 = pairs[p*2 + 1];
            int b  = p / NP;
            const float* hl = hs + ((size_t)b*SEQ + l0)*DIM;
            const float* hr = hs + ((size_t)b*SEQ + r0)*DIM;
            int k = tid * 4;
            float4 vl = *(const float4*)(hl + k);
            float4 vr = *(const float4*)(hr + k);
            __half2 l01 = __floats2half2_rn(vl.x, vl.y);
            __half2 l23 = __floats2half2_rn(vl.z, vl.w);
            __half2 r01 = __floats2half2_rn(vr.x, vr.y);
            __half2 r23 = __floats2half2_rn(vr.z, vr.w);
            size_t aL = frag16_addr(p, k, K1);
            size_t aR = frag16_addr(p, DIM + k, K1);
            *(__half2*)(g_lr + aL)     = l01;
            *(__half2*)(g_lr + aL + 8) = l23;
            *(__half2*)(g_lr + aR)     = r01;
            *(__half2*)(g_lr + aR + 8) = r23;
        }
    } else {
        int loc = bx - 3992;
        int l = loc / 3, sub = loc % 3;
        float* sp = smem_t;
        for (int t2 = tid; t2 < PE; t2 += 256) sp[t2] = pos[l*PE + t2];
        __syncthreads();
        int j = sub*256 + tid;
        float acc = b1[j];
        const float* w = W1 + (size_t)K1*DIM + j;
        #pragma unroll 8
        for (int t2 = 0; t2 < PE; t2++) acc += sp[t2] * w[(size_t)t2*DIM];
        g_P[l*DIM + j] = acc;
    }
}

/* =================== LN kernels: 192 thr x 4 consecutive j =============== */
__device__ __forceinline__ void block_reduce2_192(float& s, float& sq) {
    __shared__ float ss[6], ssq[6];
    #pragma unroll
    for (int o = 16; o > 0; o >>= 1) {
        s  += __shfl_xor_sync(0xffffffffu, s,  o);
        sq += __shfl_xor_sync(0xffffffffu, sq, o);
    }
    int w = threadIdx.x >> 5;
    if ((threadIdx.x & 31) == 0) { ss[w] = s; ssq[w] = sq; }
    __syncthreads();
    s = 0.f; sq = 0.f;
    #pragma unroll
    for (int i = 0; i < 6; i++) { s += ss[i]; sq += ssq[i]; }
}

__global__ void __launch_bounds__(192) k_fuse1(const float* __restrict__ part,
                        const float* __restrict__ g1, const float* __restrict__ be1) {
    int r = blockIdx.x;
    int p = r / SPAN, l = r % SPAN;
    int j = threadIdx.x * 4;
    float4 a4 = *(const float4*)(g_P + (size_t)l*DIM + j);
    float a[4] = {a4.x, a4.y, a4.z, a4.w};
    #pragma unroll
    for (int z = 0; z < 8; z++) {
        float4 pz = *(const float4*)(part + (size_t)z*(NB*DIM) + (size_t)p*DIM + j);
        a[0] += pz.x; a[1] += pz.y; a[2] += pz.z; a[3] += pz.w;
    }
    float v[4];
    float s = 0.f, sq = 0.f;
    #pragma unroll
    for (int q = 0; q < 4; q++) {
        v[q] = gelu_exact(a[q]); s += v[q]; sq += v[q]*v[q];
    }
    block_reduce2_192(s, sq);
    float mean = s * (1.0f/DIM);
    float var  = sq * (1.0f/DIM) - mean*mean;
    float rstd = rsqrtf(var + 1e-12f);
    float4 gg = *(const float4*)(g1 + j);
    float4 bb = *(const float4*)(be1 + j);
    float o0 = (v[0]-mean)*rstd*gg.x + bb.x;
    float o1 = (v[1]-mean)*rstd*gg.y + bb.y;
    float o2 = (v[2]-mean)*rstd*gg.z + bb.z;
    float o3 = (v[3]-mean)*rstd*gg.w + bb.w;
    size_t ad = frag16_addr(r, j, DIM);
    *(__half2*)(g_h1 + ad)     = __floats2half2_rn(o0, o1);
    *(__half2*)(g_h1 + ad + 8) = __floats2half2_rn(o2, o3);
}

__global__ void __launch_bounds__(192) k_gelu_ln(const float* __restrict__ in,
                          const float* __restrict__ g, const float* __restrict__ be) {
    int r = blockIdx.x;
    int j = threadIdx.x * 4;
    float4 a4 = *(const float4*)(in + (size_t)r*DIM + j);
    float v[4];
    float s = 0.f, sq = 0.f;
    v[0] = gelu_exact(a4.x); v[1] = gelu_exact(a4.y);
    v[2] = gelu_exact(a4.z); v[3] = gelu_exact(a4.w);
    #pragma unroll
    for (int q = 0; q < 4; q++) { s += v[q]; sq += v[q]*v[q]; }
    block_reduce2_192(s, sq);
    float mean = s * (1.0f/DIM);
    float var  = sq * (1.0f/DIM) - mean*mean;
    float rstd = rsqrtf(var + 1e-12f);
    float4 gg = *(const float4*)(g + j);
    float4 bb = *(const float4*)(be + j);
    float o0 = (v[0]-mean)*rstd*gg.x + bb.x;
    float o1 = (v[1]-mean)*rstd*gg.y + bb.y;
    float o2 = (v[2]-mean)*rstd*gg.z + bb.z;
    float o3 = (v[3]-mean)*rstd*gg.w + bb.w;
    size_t ad = frag16_addr(r, j, DIM);
    *(__half2*)(g_h2 + ad)     = __floats2half2_rn(o0, o1);
    *(__half2*)(g_h2 + ad + 8) = __floats2half2_rn(o2, o3);
}

__global__ void __launch_bounds__(256) k_reduceh3(const float* __restrict__ part,
                                                  const float* __restrict__ bp) {
    int i = (blockIdx.x*256 + threadIdx.x) * 4;
    float4 b4 = *(const float4*)(bp + (i & 127));
    float s0 = b4.x, s1 = b4.y, s2 = b4.z, s3 = b4.w;
    #pragma unroll
    for (int z = 0; z < 4; z++) {
        float4 pz = *(const float4*)(part + (size_t)z*(NR*EMB) + i);
        s0 += pz.x; s1 += pz.y; s2 += pz.z; s3 += pz.w;
    }
    size_t ad = frag16_addr(i >> 7, i & 127, EMB);
    *(__half2*)(g_h3 + ad)     = __floats2half2_rn(s0, s1);
    *(__half2*)(g_h3 + ad + 8) = __floats2half2_rn(s2, s3);
}

/* ---------------- host launch ---------------- */
extern "C" void kernel_launch(void* const* d_in, const int* in_sizes, int n_in,
                              void* d_out, int out_size) {
    const float* hs    = (const float*)d_in[0];
    const int*   pairs = (const int*)  d_in[1];
    const float* pos   = (const float*)d_in[2];
    const float* W1    = (const float*)d_in[3];
    const float* b1    = (const float*)d_in[4];
    const float* g1    = (const float*)d_in[5];
    const float* be1   = (const float*)d_in[6];
    const float* W2    = (const float*)d_in[7];
    const float* b2    = (const float*)d_in[8];
    const float* g2    = (const float*)d_in[9];
    const float* be2   = (const float*)d_in[10];
    const float* Wp    = (const float*)d_in[11];
    const float* bp    = (const float*)d_in[12];
    const float* Wdec  = (const float*)d_in[13];
    float* out = (float*)d_out;
    (void)in_sizes; (void)n_in; (void)out_size;

    __half *p_lr, *p_h1, *p_h2, *p_h3, *p_W1T, *p_W2T, *p_WpT, *p_Wd;
    float *p_pre2;
    cudaGetSymbolAddress((void**)&p_lr,   g_lr);
    cudaGetSymbolAddress((void**)&p_h1,   g_h1);
    cudaGetSymbolAddress((void**)&p_h2,   g_h2);
    cudaGetSymbolAddress((void**)&p_h3,   g_h3);
    cudaGetSymbolAddress((void**)&p_W1T,  g_W1T);
    cudaGetSymbolAddress((void**)&p_W2T,  g_W2T);
    cudaGetSymbolAddress((void**)&p_WpT,  g_WpT);
    cudaGetSymbolAddress((void**)&p_Wd,   g_Wd);
    cudaGetSymbolAddress((void**)&p_pre2, g_pre2);

    const int MSMEM = 6 * 8192 * 2;   /* 98304 B */
    const int M4SM  = 4 * 8192 * 2;   /* 65536 B */
    cudaFuncSetAttribute(mgemm16<192>, cudaFuncAttributeMaxDynamicSharedMemorySize, MSMEM);
    cudaFuncSetAttribute(mgemm16<768>, cudaFuncAttributeMaxDynamicSharedMemorySize, MSMEM);
    cudaFuncSetAttribute(mgemm4,       cudaFuncAttributeMaxDynamicSharedMemorySize, M4SM);

    /* 0) one fused producer launch */
    k_prep<<<PREP_GRID, 256>>>(hs, pairs, pos, W1, b1, W2, Wp, Wdec);

    /* 1) A-partials = g_lr @ W1[0:1536]  split-K x8 (into g_pre2) */
    mgemm16<192><<<dim3(DIM/128, NB/128, 8), 256, MSMEM>>>(
        p_lr, K1, p_W1T, K1, DIM, p_pre2, DIM, nullptr, NB*DIM);

    /* 2) h1 = LN(gelu(sum partials + P)) -> FRAG16 */
    k_fuse1<<<NR, 192>>>(p_pre2, g1, be1);

    /* 3) pre2 = h1 @ W2 + b2 ; h2 = LN(gelu(pre2)) -> FRAG16 */
    mgemm16<768><<<dim3(DIM/128, NR/128, 1), 256, MSMEM>>>(
        p_h1, DIM, p_W2T, DIM, DIM, p_pre2, DIM, b2, 0);
    k_gelu_ln<<<NR, 192>>>(p_pre2, g2, be2);

    /* 4) h3 = h2 @ Wp + bp  split-K x4 -> FRAG16 via reduce */
    mgemm16<192><<<dim3(EMB/128, NR/128, 4), 256, MSMEM>>>(
        p_h2, DIM, p_WpT, DIM, EMB, p_pre2, EMB, nullptr, NR*EMB);
    k_reduceh3<<<(NR*EMB)/1024, 256>>>(p_pre2, bp);

    /* 5) out = h3 @ Wd^T : persistent-B strip kernel */
    mgemm4<<<dim3(VROWS/128, NR/128/STRIP, 1), 256, M4SM>>>(
        p_h3, p_Wd, VOCAB, out, VOCAB);
}